// round 14
// baseline (speedup 1.0000x reference)
#include <cuda_runtime.h>
#include <cuda_fp16.h>
#include <stdint.h>
#include <math.h>

// Problem constants
#define BB   4
#define SS   2048
#define DD   1024
#define DFF  4096
#define EE   8
#define NN   (BB*SS)          // 8192 tokens
#define KTOP 2
#define SLOTS (NN*KTOP)       // 16384
#define CAP  1280
#define EPS_F 1e-9f
#define NSPLIT2 4             // split-K factor for GEMM2

// ---------------- device scratch ----------------
__device__ float    g_Part[NSPLIT2 * EE * CAP * DD];  // GEMM2 split-K partials
__device__ unsigned g_Xh[EE * CAP * DD / 2];      // dispatched X, fp16x2
__device__ unsigned g_Hh[EE * CAP * DFF / 2];     // hidden, fp16x2
__device__ unsigned g_W1h[EE * DFF * DD / 2];     // W1 as fp16x2
__device__ unsigned g_W2h[EE * DD * DFF / 2];     // W2 as fp16x2
__device__ int   g_slot_expert[SLOTS];
__device__ int   g_slot_pos[SLOTS];
__device__ float g_slot_p[SLOTS];
__device__ float g_slot_w[SLOTS];
__device__ int   g_cnt[EE];
__device__ float g_imp[EE];

// ---------------- helpers ----------------
__device__ __forceinline__ unsigned packh(__half a, __half b)
{
    return ((unsigned)__half_as_ushort(b) << 16) | (unsigned)__half_as_ushort(a);
}

__device__ __forceinline__ void mma16816h(float c[4], const uint32_t a[4], const uint32_t b[2])
{
    asm volatile(
        "mma.sync.aligned.m16n8k16.row.col.f32.f16.f16.f32 "
        "{%0,%1,%2,%3},{%4,%5,%6,%7},{%8,%9},{%0,%1,%2,%3};\n"
        : "+f"(c[0]), "+f"(c[1]), "+f"(c[2]), "+f"(c[3])
        : "r"(a[0]), "r"(a[1]), "r"(a[2]), "r"(a[3]), "r"(b[0]), "r"(b[1]));
}

__device__ __forceinline__ void ldsm4(uint32_t r[4], uint32_t saddr)
{
    asm volatile("ldmatrix.sync.aligned.m8n8.x4.shared.b16 {%0,%1,%2,%3}, [%4];"
                 : "=r"(r[0]), "=r"(r[1]), "=r"(r[2]), "=r"(r[3]) : "r"(saddr));
}

__device__ __forceinline__ void cpa16(uint32_t saddr, const void* g)
{
    asm volatile("cp.async.cg.shared.global [%0], [%1], 16;\n" :: "r"(saddr), "l"(g));
}
__device__ __forceinline__ void cpa_commit() { asm volatile("cp.async.commit_group;\n"); }

__device__ __forceinline__ uint32_t smem_u32(const void* p) {
    uint32_t a;
    asm("{ .reg .u64 t; cvta.to.shared.u64 t, %1; cvt.u32.u64 %0, t; }" : "=r"(a) : "l"(p));
    return a;
}

// ---------------- 1) gating + fused weight conversion ----------------
__global__ void gating_kernel(const float* __restrict__ x, const float* __restrict__ Wg,
                              const float* __restrict__ W1, const float* __restrict__ W2)
{
    int t = blockIdx.x;
    int tid = threadIdx.x;                  // 128 threads
    const float4* xv = (const float4*)(x + (size_t)t * DD);

    float acc[EE];
#pragma unroll
    for (int e = 0; e < EE; e++) acc[e] = 0.f;

    for (int i = tid; i < DD / 4; i += 128) {
        float4 xx = xv[i];
#pragma unroll
        for (int e = 0; e < EE; e++) {
            float4 wv = *(const float4*)(Wg + (size_t)e * DD + i * 4);
            acc[e] += xx.x * wv.x + xx.y * wv.y + xx.z * wv.z + xx.w * wv.w;
        }
    }

    __shared__ float sh[EE][128];
#pragma unroll
    for (int e = 0; e < EE; e++) sh[e][tid] = acc[e];
    __syncthreads();
    for (int s = 64; s > 0; s >>= 1) {
        if (tid < s) {
#pragma unroll
            for (int e = 0; e < EE; e++) sh[e][tid] += sh[e][tid + s];
        }
        __syncthreads();
    }

    if (tid == 0) {
        float v[EE];
#pragma unroll
        for (int e = 0; e < EE; e++) v[e] = sh[e][0];
        int i0 = 0; float s0 = v[0];
#pragma unroll
        for (int e = 1; e < EE; e++) if (v[e] > s0) { s0 = v[e]; i0 = e; }
        int i1 = -1; float s1 = -INFINITY;
#pragma unroll
        for (int e = 0; e < EE; e++) if (e != i0 && v[e] > s1) { s1 = v[e]; i1 = e; }
        float e1 = expf(s1 - s0);
        float denom = 1.f + e1;
        g_slot_expert[2 * t + 0] = i0;
        g_slot_expert[2 * t + 1] = i1;
        g_slot_p[2 * t + 0] = 1.f / denom;
        g_slot_p[2 * t + 1] = e1 / denom;
    }

    // --- fused weight conversion (grid-stride over both weight tensors) ---
    {
        const int n2 = EE * DFF * DD / 2;       // u32-pair count per tensor
        int gidx = blockIdx.x * 128 + tid;
        int gstride = gridDim.x * 128;
        for (int j = gidx; j < n2; j += gstride) {
            float2 v1 = ((const float2*)W1)[j];
            g_W1h[j] = packh(__float2half_rn(v1.x), __float2half_rn(v1.y));
            float2 v2 = ((const float2*)W2)[j];
            g_W2h[j] = packh(__float2half_rn(v2.x), __float2half_rn(v2.y));
        }
    }
}

// ---------------- 2) ordered capacity assignment ----------------
__global__ void assign_kernel()
{
    const int T = 256;
    const int CH = SLOTS / T;
    int tid = threadIdx.x;
    int base = tid * CH;

    __shared__ int   scnt[T][EE];
    __shared__ float simp[T][EE];

    int lc[EE];
#pragma unroll
    for (int e = 0; e < EE; e++) lc[e] = 0;
    for (int i = 0; i < CH; i++) lc[g_slot_expert[base + i]]++;
#pragma unroll
    for (int e = 0; e < EE; e++) scnt[tid][e] = lc[e];
    __syncthreads();

    if (tid < EE) {
        int e = tid, run = 0;
        for (int t2 = 0; t2 < T; t2++) { int c = scnt[t2][e]; scnt[t2][e] = run; run += c; }
        g_cnt[e] = min(run, CAP);
    }
    __syncthreads();

    int off[EE];
    float impl[EE];
#pragma unroll
    for (int e = 0; e < EE; e++) { off[e] = scnt[tid][e]; impl[e] = 0.f; }

    for (int i = 0; i < CH; i += 2) {
        int sA = base + i, sBs = base + i + 1;
        int e0 = g_slot_expert[sA], e1 = g_slot_expert[sBs];
        int p0 = off[e0]++;
        int p1 = off[e1]++;
        bool k0 = p0 < CAP, k1 = p1 < CAP;
        float w0 = k0 ? g_slot_p[sA] : 0.f;
        float w1 = k1 ? g_slot_p[sBs] : 0.f;
        float s = w0 + w1 + EPS_F;
        w0 /= s; w1 /= s;
        bool v0 = w0 > 0.f, v1 = w1 > 0.f;
        g_slot_w[sA] = w0;
        g_slot_w[sBs] = w1;
        g_slot_pos[sA]  = v0 ? p0 : -1;
        g_slot_pos[sBs] = v1 ? p1 : -1;
        if (v0) impl[e0] += w0;
        if (v1) impl[e1] += w1;
    }
#pragma unroll
    for (int e = 0; e < EE; e++) simp[tid][e] = impl[e];
    __syncthreads();
    if (tid < EE) {
        int e = tid;
        float s = 0.f;
        for (int t2 = 0; t2 < T; t2++) s += simp[t2][e];
        g_imp[e] = s;
    }
}

// ---------------- 3) dispatch: X -> fp16 ----------------
__global__ void dispatch_kernel(const float* __restrict__ x)
{
    int slot = blockIdx.x;
    int pos = g_slot_pos[slot];
    if (pos < 0) return;
    int e = g_slot_expert[slot];
    float w = g_slot_w[slot];
    int tok = slot >> 1;
    const float4* xs = (const float4*)(x + (size_t)tok * DD);
    size_t rowbase = ((size_t)(e * CAP + pos)) * (DD / 2);
    int i = threadIdx.x;                    // 256 threads
    float4 v = xs[i];
    g_Xh[rowbase + 2 * i + 0] = packh(__float2half_rn(v.x * w), __float2half_rn(v.y * w));
    g_Xh[rowbase + 2 * i + 1] = packh(__float2half_rn(v.z * w), __float2half_rn(v.w * w));
}

// ---------------- ldmatrix + mma.sync NT GEMM (single fp16 product) ----------------
// C[m,n] = sum_k A[m,k]*B[n,k].  CTA tile 128x128x64, 8 warps (2x4), warp 64x32.
// 3-stage cp.async ring, one __syncthreads per 64-K chunk; 2 CTAs/SM.
#define PITCH 36                   // u32 per 64-fp16 row (32 data + 4 pad); LDSM conflict-free
#define A_U32 (128 * PITCH)        // A per stage: 4608 u32 (18 KB)
#define B_U32 (128 * PITCH)        // B per stage: 4608 u32 (18 KB)
#define STAGE_U32 (A_U32 + B_U32)  // 9216 u32 (36 KB)
#define NSTAGE 3
#define GEMM_SMEM_BYTES (NSTAGE * STAGE_U32 * 4)   // 110592 B
static_assert(2 * GEMM_SMEM_BYTES <= 227 * 1024, "smem for 2 CTAs");

template<bool FUSE_RELU_H>
__global__ __launch_bounds__(256, 2)
void gemm_tc_kernel(const unsigned* __restrict__ Ah, const unsigned* __restrict__ Bh,
                    float* __restrict__ Cf, unsigned* __restrict__ Ch,
                    int Nn, int Kfull, int Klen, int nsplit, long long partStride,
                    int strideA2, int strideB2, int strideC)
{
    extern __shared__ unsigned smem[];

    int zs = blockIdx.z;
    int e  = zs / nsplit;
    int sp = zs - e * nsplit;
    int M = g_cnt[e];
    int m0 = blockIdx.y * 128;
    if (m0 >= M) return;
    int n0 = blockIdx.x * 128;
    int K2 = Kfull >> 1;
    int k0_2 = sp * (Klen >> 1);

    const unsigned* Ap = Ah + (size_t)e * strideA2 + k0_2;
    const unsigned* Bp = Bh + (size_t)e * strideB2 + k0_2;

    int tid = threadIdx.x;
    int lane = tid & 31, warp = tid >> 5;
    int wm = warp >> 2, wn = warp & 3;      // 2 x 4 warps, warp tile 64x32

    uint32_t sbase = smem_u32(smem);

    // loader mapping: 2 threads/row; thread covers u32 [c0, c0+16)
    int lrow = tid >> 1;                    // 0..127
    int c0 = (tid & 1) * 16;
    int gm = m0 + lrow;
    int gmc = min(gm, M - 1);

    // LDSM per-lane geometry
    int aRow  = wm * 64 + (lane & 15);            // + mi*16
    int aHalf = lane >> 4;                        // k-half 0/1
    int bRow  = wn * 32 + (lane & 7) + ((lane >> 4) << 3);  // + ni2*16
    int bHalf = (lane >> 3) & 1;

    float acc[4][4][4];
#pragma unroll
    for (int mi = 0; mi < 4; mi++)
#pragma unroll
        for (int ni = 0; ni < 4; ni++)
#pragma unroll
            for (int q = 0; q < 4; q++) acc[mi][ni][q] = 0.f;

    int nch = Klen / 64;

    auto issue = [&](int it) {
        uint32_t soff = (uint32_t)(it % NSTAGE) * STAGE_U32;
        int kt2 = it * 32;
        // A: 128 rows x 32 u32 = 256 threads x 16 u32 (four cpa16)
        {
            uint32_t dst = sbase + (uint32_t)(soff + lrow * PITCH + c0) * 4;
            size_t ga = (size_t)gmc * K2 + kt2 + c0;
            cpa16(dst,      Ap + ga);
            cpa16(dst + 16, Ap + ga + 4);
            cpa16(dst + 32, Ap + ga + 8);
            cpa16(dst + 48, Ap + ga + 12);
        }
        // B: 128 rows x 32 u32 likewise
        {
            uint32_t dst = sbase + (uint32_t)(soff + A_U32 + lrow * PITCH + c0) * 4;
            size_t gb = (size_t)(n0 + lrow) * K2 + kt2 + c0;
            cpa16(dst,      Bp + gb);
            cpa16(dst + 16, Bp + gb + 4);
            cpa16(dst + 32, Bp + gb + 8);
            cpa16(dst + 48, Bp + gb + 12);
        }
        cpa_commit();
    };

    issue(0);
    issue(1);

    for (int it = 0; it < nch; it++) {
        if (it + 1 < nch) asm volatile("cp.async.wait_group 1;\n" ::: "memory");
        else              asm volatile("cp.async.wait_group 0;\n" ::: "memory");
        __syncthreads();   // stage it ready; stage (it-1)%3 free for refill

        if (it + 2 < nch) issue(it + 2);

        uint32_t sA = sbase + (uint32_t)((it % NSTAGE) * STAGE_U32) * 4;
        uint32_t sB = sA + A_U32 * 4;

#pragma unroll
        for (int ks = 0; ks < 4; ks++) {
            int kb = ks * 8;
            uint32_t bh[2][4];
#pragma unroll
            for (int n2 = 0; n2 < 2; n2++) {
                uint32_t ao = (uint32_t)((bRow + n2 * 16) * PITCH + kb + bHalf * 4) * 4;
                ldsm4(bh[n2], sB + ao);
            }
#pragma unroll
            for (int mi = 0; mi < 4; mi++) {
                uint32_t ah[4];
                uint32_t ao = (uint32_t)((aRow + mi * 16) * PITCH + kb + aHalf * 4) * 4;
                ldsm4(ah, sA + ao);
#pragma unroll
                for (int ni = 0; ni < 4; ni++) {
                    mma16816h(acc[mi][ni], ah, &bh[ni >> 1][(ni & 1) * 2]);
                }
            }
        }
    }

    // --- epilogue ---
#pragma unroll
    for (int mi = 0; mi < 4; mi++) {
#pragma unroll
        for (int ni = 0; ni < 4; ni++) {
            int r0 = m0 + wm * 64 + mi * 16 + (lane >> 2);
            int cc = n0 + wn * 32 + ni * 8 + 2 * (lane & 3);
            float* a = acc[mi][ni];
            if (FUSE_RELU_H) {
                size_t eoff = (size_t)e * ((size_t)CAP * (Nn >> 1));
                if (r0 < M) {
                    Ch[eoff + (size_t)r0 * (Nn >> 1) + (cc >> 1)] =
                        packh(__float2half_rn(fmaxf(a[0], 0.f)), __float2half_rn(fmaxf(a[1], 0.f)));
                }
                if (r0 + 8 < M) {
                    Ch[eoff + (size_t)(r0 + 8) * (Nn >> 1) + (cc >> 1)] =
                        packh(__float2half_rn(fmaxf(a[2], 0.f)), __float2half_rn(fmaxf(a[3], 0.f)));
                }
            } else {
                float* Cp = Cf + (long long)sp * partStride + (size_t)e * strideC;
                if (r0 < M)
                    *(float2*)(Cp + (size_t)r0 * Nn + cc) = make_float2(a[0], a[1]);
                if (r0 + 8 < M)
                    *(float2*)(Cp + (size_t)(r0 + 8) * Nn + cc) = make_float2(a[2], a[3]);
            }
        }
    }
}

// ---------------- 6) combine: sum split-K partials over kept slots ----------------
__global__ void combine_kernel(float* __restrict__ y)
{
    int t = blockIdx.x;
    int i = threadIdx.x;
    const long long PS = (long long)EE * CAP * DD;
    float4 acc = make_float4(0.f, 0.f, 0.f, 0.f);
#pragma unroll
    for (int j = 0; j < KTOP; j++) {
        int slot = t * KTOP + j;
        int pos = g_slot_pos[slot];
        if (pos >= 0) {
            int e = g_slot_expert[slot];
            size_t rb = ((size_t)(e * CAP + pos)) * DD;
#pragma unroll
            for (int s = 0; s < NSPLIT2; s++) {
                const float4* o = (const float4*)(g_Part + s * PS + rb);
                float4 v = o[i];
                acc.x += v.x; acc.y += v.y; acc.z += v.z; acc.w += v.w;
            }
        }
    }
    ((float4*)(y + (size_t)t * DD))[i] = acc;
}

// ---------------- 7) aux loss ----------------
__global__ void aux_kernel(float* __restrict__ out, int out_size)
{
    float tc = 0.f, ic = 0.f;
#pragma unroll
    for (int e = 0; e < EE; e++) { tc += (float)g_cnt[e]; ic += g_imp[e]; }
    float aux = 0.f;
#pragma unroll
    for (int e = 0; e < EE; e++) aux += ((float)g_cnt[e] / tc) * (g_imp[e] / ic);
    out[out_size - 1] = aux * (float)EE;
}

// ---------------- launch ----------------
extern "C" void kernel_launch(void* const* d_in, const int* in_sizes, int n_in,
                              void* d_out, int out_size)
{
    const float* x  = (const float*)d_in[0];
    const float* Wg = (const float*)d_in[1];
    const float* W1 = (const float*)d_in[2];
    const float* W2 = (const float*)d_in[3];
    float* y = (float*)d_out;
    (void)in_sizes; (void)n_in;

    cudaFuncSetAttribute(gemm_tc_kernel<true>,  cudaFuncAttributeMaxDynamicSharedMemorySize, GEMM_SMEM_BYTES);
    cudaFuncSetAttribute(gemm_tc_kernel<false>, cudaFuncAttributeMaxDynamicSharedMemorySize, GEMM_SMEM_BYTES);

    unsigned *Xh, *Hh, *W1h, *W2h;
    float *Part;
    cudaGetSymbolAddress((void**)&Xh,  g_Xh);
    cudaGetSymbolAddress((void**)&Hh,  g_Hh);
    cudaGetSymbolAddress((void**)&W1h, g_W1h);
    cudaGetSymbolAddress((void**)&W2h, g_W2h);
    cudaGetSymbolAddress((void**)&Part, g_Part);

    // launch order: GEMM1 is the 4th kernel launch -> ncu captures it
    gating_kernel<<<NN, 128>>>(x, Wg, W1, W2);                           // 1 (+ fused wconv)
    assign_kernel<<<1, 256>>>();                                         // 2
    dispatch_kernel<<<SLOTS, 256>>>(x);                                  // 3

    // GEMM1: H = relu(X @ W1^T); per expert M=cnt, N=DFF, K=DD; fused relu+fp16 store
    {
        dim3 grid(DFF / 128, CAP / 128, EE);                             // 4 (profiled)
        gemm_tc_kernel<true><<<grid, 256, GEMM_SMEM_BYTES>>>(
            Xh, W1h, nullptr, Hh,
            DFF, DD, DD, 1, 0,
            CAP * DD / 2, DFF * DD / 2, 0);
    }

    // GEMM2: Part[s] = H[:, s*1024:(s+1)*1024] @ W2[:, slice]^T (split-K x4)
    {
        dim3 grid(DD / 128, CAP / 128, EE * NSPLIT2);                    // 5
        gemm_tc_kernel<false><<<grid, 256, GEMM_SMEM_BYTES>>>(
            Hh, W2h, Part, nullptr,
            DD, DFF, DFF / NSPLIT2, NSPLIT2, (long long)EE * CAP * DD,
            CAP * DFF / 2, DD * DFF / 2, CAP * DD);
    }

    combine_kernel<<<NN, 256>>>(y);                                      // 6
    aux_kernel<<<1, 1>>>(y, out_size);                                   // 7
}

// round 15
// speedup vs baseline: 1.1199x; 1.1199x over previous
#include <cuda_runtime.h>
#include <cuda_fp16.h>
#include <stdint.h>
#include <math.h>

// Problem constants
#define BB   4
#define SS   2048
#define DD   1024
#define DFF  4096
#define EE   8
#define NN   (BB*SS)          // 8192 tokens
#define KTOP 2
#define SLOTS (NN*KTOP)       // 16384
#define CAP  1280
#define EPS_F 1e-9f
#define NSPLIT2 4             // split-K factor for GEMM2

// ---------------- device scratch ----------------
__device__ float    g_Part[NSPLIT2 * EE * CAP * DD];  // GEMM2 split-K partials
__device__ unsigned g_Xh[EE * CAP * DD / 2];      // dispatched X, fp16x2
__device__ unsigned g_Hh[EE * CAP * DFF / 2];     // hidden, fp16x2
__device__ unsigned g_W1h[EE * DFF * DD / 2];     // W1 as fp16x2
__device__ unsigned g_W2h[EE * DD * DFF / 2];     // W2 as fp16x2
__device__ int   g_slot_expert[SLOTS];
__device__ int   g_slot_pos[SLOTS];
__device__ float g_slot_p[SLOTS];
__device__ float g_slot_w[SLOTS];
__device__ int   g_cnt[EE];
__device__ float g_imp[EE];

// ---------------- helpers ----------------
__device__ __forceinline__ unsigned packh(__half a, __half b)
{
    return ((unsigned)__half_as_ushort(b) << 16) | (unsigned)__half_as_ushort(a);
}

__device__ __forceinline__ void mma16816h(float c[4], const uint32_t a[4], const uint32_t b[2])
{
    asm volatile(
        "mma.sync.aligned.m16n8k16.row.col.f32.f16.f16.f32 "
        "{%0,%1,%2,%3},{%4,%5,%6,%7},{%8,%9},{%0,%1,%2,%3};\n"
        : "+f"(c[0]), "+f"(c[1]), "+f"(c[2]), "+f"(c[3])
        : "r"(a[0]), "r"(a[1]), "r"(a[2]), "r"(a[3]), "r"(b[0]), "r"(b[1]));
}

__device__ __forceinline__ void ldsm4(uint32_t r[4], uint32_t saddr)
{
    asm volatile("ldmatrix.sync.aligned.m8n8.x4.shared.b16 {%0,%1,%2,%3}, [%4];"
                 : "=r"(r[0]), "=r"(r[1]), "=r"(r[2]), "=r"(r[3]) : "r"(saddr));
}

__device__ __forceinline__ void cpa16(uint32_t saddr, const void* g)
{
    asm volatile("cp.async.cg.shared.global [%0], [%1], 16;\n" :: "r"(saddr), "l"(g));
}
__device__ __forceinline__ void cpa_commit() { asm volatile("cp.async.commit_group;\n"); }

__device__ __forceinline__ uint32_t smem_u32(const void* p) {
    uint32_t a;
    asm("{ .reg .u64 t; cvta.to.shared.u64 t, %1; cvt.u32.u64 %0, t; }" : "=r"(a) : "l"(p));
    return a;
}

// ---------------- 1) gating + fused weight conversion ----------------
__global__ void gating_kernel(const float* __restrict__ x, const float* __restrict__ Wg,
                              const float* __restrict__ W1, const float* __restrict__ W2)
{
    int t = blockIdx.x;
    int tid = threadIdx.x;                  // 128 threads
    const float4* xv = (const float4*)(x + (size_t)t * DD);

    float acc[EE];
#pragma unroll
    for (int e = 0; e < EE; e++) acc[e] = 0.f;

    for (int i = tid; i < DD / 4; i += 128) {
        float4 xx = xv[i];
#pragma unroll
        for (int e = 0; e < EE; e++) {
            float4 wv = *(const float4*)(Wg + (size_t)e * DD + i * 4);
            acc[e] += xx.x * wv.x + xx.y * wv.y + xx.z * wv.z + xx.w * wv.w;
        }
    }

    __shared__ float sh[EE][128];
#pragma unroll
    for (int e = 0; e < EE; e++) sh[e][tid] = acc[e];
    __syncthreads();
    for (int s = 64; s > 0; s >>= 1) {
        if (tid < s) {
#pragma unroll
            for (int e = 0; e < EE; e++) sh[e][tid] += sh[e][tid + s];
        }
        __syncthreads();
    }

    if (tid == 0) {
        float v[EE];
#pragma unroll
        for (int e = 0; e < EE; e++) v[e] = sh[e][0];
        int i0 = 0; float s0 = v[0];
#pragma unroll
        for (int e = 1; e < EE; e++) if (v[e] > s0) { s0 = v[e]; i0 = e; }
        int i1 = -1; float s1 = -INFINITY;
#pragma unroll
        for (int e = 0; e < EE; e++) if (e != i0 && v[e] > s1) { s1 = v[e]; i1 = e; }
        float e1 = expf(s1 - s0);
        float denom = 1.f + e1;
        g_slot_expert[2 * t + 0] = i0;
        g_slot_expert[2 * t + 1] = i1;
        g_slot_p[2 * t + 0] = 1.f / denom;
        g_slot_p[2 * t + 1] = e1 / denom;
    }

    // --- fused weight conversion (grid-stride over both weight tensors) ---
    {
        const int n2 = EE * DFF * DD / 2;       // u32-pair count per tensor
        int gidx = blockIdx.x * 128 + tid;
        int gstride = gridDim.x * 128;
        for (int j = gidx; j < n2; j += gstride) {
            float2 v1 = ((const float2*)W1)[j];
            g_W1h[j] = packh(__float2half_rn(v1.x), __float2half_rn(v1.y));
            float2 v2 = ((const float2*)W2)[j];
            g_W2h[j] = packh(__float2half_rn(v2.x), __float2half_rn(v2.y));
        }
    }
}

// ---------------- 2) ordered capacity assignment ----------------
__global__ void assign_kernel()
{
    const int T = 256;
    const int CH = SLOTS / T;
    int tid = threadIdx.x;
    int base = tid * CH;

    __shared__ int   scnt[T][EE];
    __shared__ float simp[T][EE];

    int lc[EE];
#pragma unroll
    for (int e = 0; e < EE; e++) lc[e] = 0;
    for (int i = 0; i < CH; i++) lc[g_slot_expert[base + i]]++;
#pragma unroll
    for (int e = 0; e < EE; e++) scnt[tid][e] = lc[e];
    __syncthreads();

    if (tid < EE) {
        int e = tid, run = 0;
        for (int t2 = 0; t2 < T; t2++) { int c = scnt[t2][e]; scnt[t2][e] = run; run += c; }
        g_cnt[e] = min(run, CAP);
    }
    __syncthreads();

    int off[EE];
    float impl[EE];
#pragma unroll
    for (int e = 0; e < EE; e++) { off[e] = scnt[tid][e]; impl[e] = 0.f; }

    for (int i = 0; i < CH; i += 2) {
        int sA = base + i, sBs = base + i + 1;
        int e0 = g_slot_expert[sA], e1 = g_slot_expert[sBs];
        int p0 = off[e0]++;
        int p1 = off[e1]++;
        bool k0 = p0 < CAP, k1 = p1 < CAP;
        float w0 = k0 ? g_slot_p[sA] : 0.f;
        float w1 = k1 ? g_slot_p[sBs] : 0.f;
        float s = w0 + w1 + EPS_F;
        w0 /= s; w1 /= s;
        bool v0 = w0 > 0.f, v1 = w1 > 0.f;
        g_slot_w[sA] = w0;
        g_slot_w[sBs] = w1;
        g_slot_pos[sA]  = v0 ? p0 : -1;
        g_slot_pos[sBs] = v1 ? p1 : -1;
        if (v0) impl[e0] += w0;
        if (v1) impl[e1] += w1;
    }
#pragma unroll
    for (int e = 0; e < EE; e++) simp[tid][e] = impl[e];
    __syncthreads();
    if (tid < EE) {
        int e = tid;
        float s = 0.f;
        for (int t2 = 0; t2 < T; t2++) s += simp[t2][e];
        g_imp[e] = s;
    }
}

// ---------------- 3) dispatch: X -> fp16 ----------------
__global__ void dispatch_kernel(const float* __restrict__ x)
{
    int slot = blockIdx.x;
    int pos = g_slot_pos[slot];
    if (pos < 0) return;
    int e = g_slot_expert[slot];
    float w = g_slot_w[slot];
    int tok = slot >> 1;
    const float4* xs = (const float4*)(x + (size_t)tok * DD);
    size_t rowbase = ((size_t)(e * CAP + pos)) * (DD / 2);
    int i = threadIdx.x;                    // 256 threads
    float4 v = xs[i];
    g_Xh[rowbase + 2 * i + 0] = packh(__float2half_rn(v.x * w), __float2half_rn(v.y * w));
    g_Xh[rowbase + 2 * i + 1] = packh(__float2half_rn(v.z * w), __float2half_rn(v.w * w));
}

// ---------------- ldmatrix + mma.sync NT GEMM (single fp16 product) ----------------
// C[m,n] = sum_k A[m,k]*B[n,k].  CTA tile 128x256x64, 16 warps (2x8), warp 64x32.
// 4-stage cp.async ring (3 chunks of prefetch), one __syncthreads per chunk.
// B fragments double-buffered across ks steps.
#define PITCH 36                   // u32 per 64-fp16 row (32 data + 4 pad); LDSM conflict-free
#define A_U32 (128 * PITCH)        // A per stage: 4608 u32 (18 KB)
#define B_U32 (256 * PITCH)        // B per stage: 9216 u32 (36 KB)
#define STAGE_U32 (A_U32 + B_U32)  // 13824 u32 (54 KB)
#define NSTAGE 4
#define GEMM_SMEM_BYTES (NSTAGE * STAGE_U32 * 4)   // 221184 B
static_assert(GEMM_SMEM_BYTES <= 227 * 1024, "smem");

template<bool FUSE_RELU_H>
__global__ __launch_bounds__(512, 1)
void gemm_tc_kernel(const unsigned* __restrict__ Ah, const unsigned* __restrict__ Bh,
                    float* __restrict__ Cf, unsigned* __restrict__ Ch,
                    int Nn, int Kfull, int Klen, int nsplit, long long partStride,
                    int strideA2, int strideB2, int strideC)
{
    extern __shared__ unsigned smem[];

    int zs = blockIdx.z;
    int e  = zs / nsplit;
    int sp = zs - e * nsplit;
    int M = g_cnt[e];
    int m0 = blockIdx.y * 128;
    if (m0 >= M) return;
    int n0 = blockIdx.x * 256;
    int K2 = Kfull >> 1;
    int k0_2 = sp * (Klen >> 1);

    const unsigned* Ap = Ah + (size_t)e * strideA2 + k0_2;
    const unsigned* Bp = Bh + (size_t)e * strideB2 + k0_2;

    int tid = threadIdx.x;
    int lane = tid & 31, warp = tid >> 5;
    int wm = warp >> 3, wn = warp & 7;      // 2 x 8 warps, warp tile 64x32

    uint32_t sbase = smem_u32(smem);

    // loader mapping: 4 threads/row; thread covers u32 [c0, c0+8)
    int lrow = tid >> 2;                    // 0..127
    int c0 = (tid & 3) * 8;
    int gm = m0 + lrow;
    int gmc = min(gm, M - 1);

    // LDSM per-lane geometry
    int aRow  = wm * 64 + (lane & 15);            // + mi*16
    int aHalf = lane >> 4;                        // k-half 0/1
    int bRow  = wn * 32 + (lane & 7) + ((lane >> 4) << 3);  // + ni2*16
    int bHalf = (lane >> 3) & 1;

    float acc[4][4][4];
#pragma unroll
    for (int mi = 0; mi < 4; mi++)
#pragma unroll
        for (int ni = 0; ni < 4; ni++)
#pragma unroll
            for (int q = 0; q < 4; q++) acc[mi][ni][q] = 0.f;

    int nch = Klen / 64;

    auto issue = [&](int it) {
        uint32_t soff = (uint32_t)(it % NSTAGE) * STAGE_U32;
        int kt2 = it * 32;
        // A: 128 rows x 32 u32 = 512 threads x 8 u32 (two cpa16)
        {
            uint32_t dst = sbase + (uint32_t)(soff + lrow * PITCH + c0) * 4;
            size_t ga = (size_t)gmc * K2 + kt2 + c0;
            cpa16(dst,      Ap + ga);
            cpa16(dst + 16, Ap + ga + 4);
        }
        // B: 256 rows x 32 u32, 2 row-segments per thread (four cpa16)
#pragma unroll
        for (int j = 0; j < 2; j++) {
            int idx = tid + j * 512;
            int r = idx >> 2;
            int cc = (idx & 3) * 8;
            uint32_t dst = sbase + (uint32_t)(soff + A_U32 + r * PITCH + cc) * 4;
            size_t gb = (size_t)(n0 + r) * K2 + kt2 + cc;
            cpa16(dst,      Bp + gb);
            cpa16(dst + 16, Bp + gb + 4);
        }
        cpa_commit();
    };

    issue(0);
    if (nch > 1) issue(1);
    if (nch > 2) issue(2);

    for (int it = 0; it < nch; it++) {
        // guarantee group `it` arrived; keep up to 2 younger groups in flight
        if (it + 2 < nch)      asm volatile("cp.async.wait_group 2;\n" ::: "memory");
        else if (it + 1 < nch) asm volatile("cp.async.wait_group 1;\n" ::: "memory");
        else                   asm volatile("cp.async.wait_group 0;\n" ::: "memory");
        __syncthreads();   // stage it ready; stage (it-1)%4 consumed & free

        if (it + 3 < nch) issue(it + 3);

        uint32_t sA = sbase + (uint32_t)((it % NSTAGE) * STAGE_U32) * 4;
        uint32_t sB = sA + A_U32 * 4;

        // B fragments double-buffered across ks
        uint32_t bb[2][2][4];
#pragma unroll
        for (int n2 = 0; n2 < 2; n2++) {
            uint32_t ao = (uint32_t)((bRow + n2 * 16) * PITCH + bHalf * 4) * 4;
            ldsm4(bb[0][n2], sB + ao);
        }

#pragma unroll
        for (int ks = 0; ks < 4; ks++) {
            if (ks < 3) {
                int kbn = (ks + 1) * 8;
#pragma unroll
                for (int n2 = 0; n2 < 2; n2++) {
                    uint32_t ao = (uint32_t)((bRow + n2 * 16) * PITCH + kbn + bHalf * 4) * 4;
                    ldsm4(bb[(ks + 1) & 1][n2], sB + ao);
                }
            }
            int kb = ks * 8;
#pragma unroll
            for (int mi = 0; mi < 4; mi++) {
                uint32_t ah[4];
                uint32_t ao = (uint32_t)((aRow + mi * 16) * PITCH + kb + aHalf * 4) * 4;
                ldsm4(ah, sA + ao);
#pragma unroll
                for (int ni = 0; ni < 4; ni++) {
                    mma16816h(acc[mi][ni], ah, &bb[ks & 1][ni >> 1][(ni & 1) * 2]);
                }
            }
        }
    }

    // --- epilogue ---
#pragma unroll
    for (int mi = 0; mi < 4; mi++) {
#pragma unroll
        for (int ni = 0; ni < 4; ni++) {
            int r0 = m0 + wm * 64 + mi * 16 + (lane >> 2);
            int cc = n0 + wn * 32 + ni * 8 + 2 * (lane & 3);
            float* a = acc[mi][ni];
            if (FUSE_RELU_H) {
                size_t eoff = (size_t)e * ((size_t)CAP * (Nn >> 1));
                if (r0 < M) {
                    Ch[eoff + (size_t)r0 * (Nn >> 1) + (cc >> 1)] =
                        packh(__float2half_rn(fmaxf(a[0], 0.f)), __float2half_rn(fmaxf(a[1], 0.f)));
                }
                if (r0 + 8 < M) {
                    Ch[eoff + (size_t)(r0 + 8) * (Nn >> 1) + (cc >> 1)] =
                        packh(__float2half_rn(fmaxf(a[2], 0.f)), __float2half_rn(fmaxf(a[3], 0.f)));
                }
            } else {
                float* Cp = Cf + (long long)sp * partStride + (size_t)e * strideC;
                if (r0 < M)
                    *(float2*)(Cp + (size_t)r0 * Nn + cc) = make_float2(a[0], a[1]);
                if (r0 + 8 < M)
                    *(float2*)(Cp + (size_t)(r0 + 8) * Nn + cc) = make_float2(a[2], a[3]);
            }
        }
    }
}

// ---------------- 6) combine: sum split-K partials over kept slots ----------------
__global__ void combine_kernel(float* __restrict__ y)
{
    int t = blockIdx.x;
    int i = threadIdx.x;
    const long long PS = (long long)EE * CAP * DD;
    float4 acc = make_float4(0.f, 0.f, 0.f, 0.f);
#pragma unroll
    for (int j = 0; j < KTOP; j++) {
        int slot = t * KTOP + j;
        int pos = g_slot_pos[slot];
        if (pos >= 0) {
            int e = g_slot_expert[slot];
            size_t rb = ((size_t)(e * CAP + pos)) * DD;
#pragma unroll
            for (int s = 0; s < NSPLIT2; s++) {
                const float4* o = (const float4*)(g_Part + s * PS + rb);
                float4 v = o[i];
                acc.x += v.x; acc.y += v.y; acc.z += v.z; acc.w += v.w;
            }
        }
    }
    ((float4*)(y + (size_t)t * DD))[i] = acc;
}

// ---------------- 7) aux loss ----------------
__global__ void aux_kernel(float* __restrict__ out, int out_size)
{
    float tc = 0.f, ic = 0.f;
#pragma unroll
    for (int e = 0; e < EE; e++) { tc += (float)g_cnt[e]; ic += g_imp[e]; }
    float aux = 0.f;
#pragma unroll
    for (int e = 0; e < EE; e++) aux += ((float)g_cnt[e] / tc) * (g_imp[e] / ic);
    out[out_size - 1] = aux * (float)EE;
}

// ---------------- launch ----------------
extern "C" void kernel_launch(void* const* d_in, const int* in_sizes, int n_in,
                              void* d_out, int out_size)
{
    const float* x  = (const float*)d_in[0];
    const float* Wg = (const float*)d_in[1];
    const float* W1 = (const float*)d_in[2];
    const float* W2 = (const float*)d_in[3];
    float* y = (float*)d_out;
    (void)in_sizes; (void)n_in;

    cudaFuncSetAttribute(gemm_tc_kernel<true>,  cudaFuncAttributeMaxDynamicSharedMemorySize, GEMM_SMEM_BYTES);
    cudaFuncSetAttribute(gemm_tc_kernel<false>, cudaFuncAttributeMaxDynamicSharedMemorySize, GEMM_SMEM_BYTES);

    unsigned *Xh, *Hh, *W1h, *W2h;
    float *Part;
    cudaGetSymbolAddress((void**)&Xh,  g_Xh);
    cudaGetSymbolAddress((void**)&Hh,  g_Hh);
    cudaGetSymbolAddress((void**)&W1h, g_W1h);
    cudaGetSymbolAddress((void**)&W2h, g_W2h);
    cudaGetSymbolAddress((void**)&Part, g_Part);

    // launch order: GEMM1 is the 4th kernel launch -> ncu captures it
    gating_kernel<<<NN, 128>>>(x, Wg, W1, W2);                           // 1 (+ fused wconv)
    assign_kernel<<<1, 256>>>();                                         // 2
    dispatch_kernel<<<SLOTS, 256>>>(x);                                  // 3

    // GEMM1: H = relu(X @ W1^T); per expert M=cnt, N=DFF, K=DD; fused relu+fp16 store
    {
        dim3 grid(DFF / 256, CAP / 128, EE);                             // 4 (profiled)
        gemm_tc_kernel<true><<<grid, 512, GEMM_SMEM_BYTES>>>(
            Xh, W1h, nullptr, Hh,
            DFF, DD, DD, 1, 0,
            CAP * DD / 2, DFF * DD / 2, 0);
    }

    // GEMM2: Part[s] = H[:, s*1024:(s+1)*1024] @ W2[:, slice]^T (split-K x4)
    {
        dim3 grid(DD / 256, CAP / 128, EE * NSPLIT2);                    // 5
        gemm_tc_kernel<false><<<grid, 512, GEMM_SMEM_BYTES>>>(
            Hh, W2h, Part, nullptr,
            DD, DFF, DFF / NSPLIT2, NSPLIT2, (long long)EE * CAP * DD,
            CAP * DFF / 2, DD * DFF / 2, CAP * DD);
    }

    combine_kernel<<<NN, 256>>>(y);                                      // 6
    aux_kernel<<<1, 1>>>(y, out_size);                                   // 7
}

// round 16
// speedup vs baseline: 1.1354x; 1.0138x over previous
#include <cuda_runtime.h>
#include <cuda_fp16.h>
#include <stdint.h>
#include <math.h>

// Problem constants
#define BB   4
#define SS   2048
#define DD   1024
#define DFF  4096
#define EE   8
#define NN   (BB*SS)          // 8192 tokens
#define KTOP 2
#define SLOTS (NN*KTOP)       // 16384
#define CAP  1280
#define EPS_F 1e-9f
#define NSPLIT2 4             // split-K factor for GEMM2

// ---------------- device scratch ----------------
__device__ unsigned g_Part[NSPLIT2 * EE * CAP * DD / 2]; // GEMM2 split-K partials (fp16x2)
__device__ unsigned g_Xh[EE * CAP * DD / 2];      // dispatched X, fp16x2
__device__ unsigned g_Hh[EE * CAP * DFF / 2];     // hidden, fp16x2
__device__ unsigned g_W1h[EE * DFF * DD / 2];     // W1 as fp16x2
__device__ unsigned g_W2h[EE * DD * DFF / 2];     // W2 as fp16x2
__device__ int   g_slot_expert[SLOTS];
__device__ int   g_slot_pos[SLOTS];
__device__ float g_slot_p[SLOTS];
__device__ float g_slot_w[SLOTS];
__device__ int   g_cnt[EE];
__device__ float g_imp[EE];

// ---------------- helpers ----------------
__device__ __forceinline__ unsigned packh(__half a, __half b)
{
    return ((unsigned)__half_as_ushort(b) << 16) | (unsigned)__half_as_ushort(a);
}

__device__ __forceinline__ void mma16816h(float c[4], const uint32_t a[4], const uint32_t b[2])
{
    asm volatile(
        "mma.sync.aligned.m16n8k16.row.col.f32.f16.f16.f32 "
        "{%0,%1,%2,%3},{%4,%5,%6,%7},{%8,%9},{%0,%1,%2,%3};\n"
        : "+f"(c[0]), "+f"(c[1]), "+f"(c[2]), "+f"(c[3])
        : "r"(a[0]), "r"(a[1]), "r"(a[2]), "r"(a[3]), "r"(b[0]), "r"(b[1]));
}

__device__ __forceinline__ void ldsm4(uint32_t r[4], uint32_t saddr)
{
    asm volatile("ldmatrix.sync.aligned.m8n8.x4.shared.b16 {%0,%1,%2,%3}, [%4];"
                 : "=r"(r[0]), "=r"(r[1]), "=r"(r[2]), "=r"(r[3]) : "r"(saddr));
}

__device__ __forceinline__ void cpa16(uint32_t saddr, const void* g)
{
    asm volatile("cp.async.cg.shared.global [%0], [%1], 16;\n" :: "r"(saddr), "l"(g));
}
__device__ __forceinline__ void cpa_commit() { asm volatile("cp.async.commit_group;\n"); }

__device__ __forceinline__ uint32_t smem_u32(const void* p) {
    uint32_t a;
    asm("{ .reg .u64 t; cvta.to.shared.u64 t, %1; cvt.u32.u64 %0, t; }" : "=r"(a) : "l"(p));
    return a;
}

// ---------------- 1) gating + fused weight conversion ----------------
__global__ void gating_kernel(const float* __restrict__ x, const float* __restrict__ Wg,
                              const float* __restrict__ W1, const float* __restrict__ W2)
{
    int t = blockIdx.x;
    int tid = threadIdx.x;                  // 128 threads
    const float4* xv = (const float4*)(x + (size_t)t * DD);

    float acc[EE];
#pragma unroll
    for (int e = 0; e < EE; e++) acc[e] = 0.f;

    for (int i = tid; i < DD / 4; i += 128) {
        float4 xx = xv[i];
#pragma unroll
        for (int e = 0; e < EE; e++) {
            float4 wv = *(const float4*)(Wg + (size_t)e * DD + i * 4);
            acc[e] += xx.x * wv.x + xx.y * wv.y + xx.z * wv.z + xx.w * wv.w;
        }
    }

    __shared__ float sh[EE][128];
#pragma unroll
    for (int e = 0; e < EE; e++) sh[e][tid] = acc[e];
    __syncthreads();
    for (int s = 64; s > 0; s >>= 1) {
        if (tid < s) {
#pragma unroll
            for (int e = 0; e < EE; e++) sh[e][tid] += sh[e][tid + s];
        }
        __syncthreads();
    }

    if (tid == 0) {
        float v[EE];
#pragma unroll
        for (int e = 0; e < EE; e++) v[e] = sh[e][0];
        int i0 = 0; float s0 = v[0];
#pragma unroll
        for (int e = 1; e < EE; e++) if (v[e] > s0) { s0 = v[e]; i0 = e; }
        int i1 = -1; float s1 = -INFINITY;
#pragma unroll
        for (int e = 0; e < EE; e++) if (e != i0 && v[e] > s1) { s1 = v[e]; i1 = e; }
        float e1 = expf(s1 - s0);
        float denom = 1.f + e1;
        g_slot_expert[2 * t + 0] = i0;
        g_slot_expert[2 * t + 1] = i1;
        g_slot_p[2 * t + 0] = 1.f / denom;
        g_slot_p[2 * t + 1] = e1 / denom;
    }

    // --- fused weight conversion (grid-stride over both weight tensors) ---
    {
        const int n2 = EE * DFF * DD / 2;       // u32-pair count per tensor
        int gidx = blockIdx.x * 128 + tid;
        int gstride = gridDim.x * 128;
        for (int j = gidx; j < n2; j += gstride) {
            float2 v1 = ((const float2*)W1)[j];
            g_W1h[j] = packh(__float2half_rn(v1.x), __float2half_rn(v1.y));
            float2 v2 = ((const float2*)W2)[j];
            g_W2h[j] = packh(__float2half_rn(v2.x), __float2half_rn(v2.y));
        }
    }
}

// ---------------- 2) ordered capacity assignment ----------------
__global__ void assign_kernel()
{
    const int T = 256;
    const int CH = SLOTS / T;
    int tid = threadIdx.x;
    int base = tid * CH;

    __shared__ int   scnt[T][EE];
    __shared__ float simp[T][EE];

    int lc[EE];
#pragma unroll
    for (int e = 0; e < EE; e++) lc[e] = 0;
    for (int i = 0; i < CH; i++) lc[g_slot_expert[base + i]]++;
#pragma unroll
    for (int e = 0; e < EE; e++) scnt[tid][e] = lc[e];
    __syncthreads();

    if (tid < EE) {
        int e = tid, run = 0;
        for (int t2 = 0; t2 < T; t2++) { int c = scnt[t2][e]; scnt[t2][e] = run; run += c; }
        g_cnt[e] = min(run, CAP);
    }
    __syncthreads();

    int off[EE];
    float impl[EE];
#pragma unroll
    for (int e = 0; e < EE; e++) { off[e] = scnt[tid][e]; impl[e] = 0.f; }

    for (int i = 0; i < CH; i += 2) {
        int sA = base + i, sBs = base + i + 1;
        int e0 = g_slot_expert[sA], e1 = g_slot_expert[sBs];
        int p0 = off[e0]++;
        int p1 = off[e1]++;
        bool k0 = p0 < CAP, k1 = p1 < CAP;
        float w0 = k0 ? g_slot_p[sA] : 0.f;
        float w1 = k1 ? g_slot_p[sBs] : 0.f;
        float s = w0 + w1 + EPS_F;
        w0 /= s; w1 /= s;
        bool v0 = w0 > 0.f, v1 = w1 > 0.f;
        g_slot_w[sA] = w0;
        g_slot_w[sBs] = w1;
        g_slot_pos[sA]  = v0 ? p0 : -1;
        g_slot_pos[sBs] = v1 ? p1 : -1;
        if (v0) impl[e0] += w0;
        if (v1) impl[e1] += w1;
    }
#pragma unroll
    for (int e = 0; e < EE; e++) simp[tid][e] = impl[e];
    __syncthreads();
    if (tid < EE) {
        int e = tid;
        float s = 0.f;
        for (int t2 = 0; t2 < T; t2++) s += simp[t2][e];
        g_imp[e] = s;
    }
}

// ---------------- 3) dispatch: X -> fp16 ----------------
__global__ void dispatch_kernel(const float* __restrict__ x)
{
    int slot = blockIdx.x;
    int pos = g_slot_pos[slot];
    if (pos < 0) return;
    int e = g_slot_expert[slot];
    float w = g_slot_w[slot];
    int tok = slot >> 1;
    const float4* xs = (const float4*)(x + (size_t)tok * DD);
    size_t rowbase = ((size_t)(e * CAP + pos)) * (DD / 2);
    int i = threadIdx.x;                    // 256 threads
    float4 v = xs[i];
    g_Xh[rowbase + 2 * i + 0] = packh(__float2half_rn(v.x * w), __float2half_rn(v.y * w));
    g_Xh[rowbase + 2 * i + 1] = packh(__float2half_rn(v.z * w), __float2half_rn(v.w * w));
}

// ---------------- ldmatrix + mma.sync NT GEMM (single fp16 product) ----------------
// C[m,n] = sum_k A[m,k]*B[n,k].  CTA tile 128x256x64, 16 warps (2x8), warp 64x32.
// 4-stage cp.async ring (3 chunks of prefetch), one __syncthreads per chunk.
// B fragments double-buffered across ks steps.  fp16 outputs (H or Part).
#define PITCH 36                   // u32 per 64-fp16 row (32 data + 4 pad); LDSM conflict-free
#define A_U32 (128 * PITCH)        // A per stage: 4608 u32 (18 KB)
#define B_U32 (256 * PITCH)        // B per stage: 9216 u32 (36 KB)
#define STAGE_U32 (A_U32 + B_U32)  // 13824 u32 (54 KB)
#define NSTAGE 4
#define GEMM_SMEM_BYTES (NSTAGE * STAGE_U32 * 4)   // 221184 B
static_assert(GEMM_SMEM_BYTES <= 227 * 1024, "smem");

template<bool FUSE_RELU_H>
__global__ __launch_bounds__(512, 1)
void gemm_tc_kernel(const unsigned* __restrict__ Ah, const unsigned* __restrict__ Bh,
                    unsigned* __restrict__ Cpart, unsigned* __restrict__ Ch,
                    int Nn, int Kfull, int Klen, int nsplit, long long partStride2,
                    int strideA2, int strideB2, int strideC2)
{
    extern __shared__ unsigned smem[];

    int zs = blockIdx.z;
    int e  = zs / nsplit;
    int sp = zs - e * nsplit;
    int M = g_cnt[e];
    int m0 = blockIdx.y * 128;
    if (m0 >= M) return;
    int n0 = blockIdx.x * 256;
    int K2 = Kfull >> 1;
    int k0_2 = sp * (Klen >> 1);

    const unsigned* Ap = Ah + (size_t)e * strideA2 + k0_2;
    const unsigned* Bp = Bh + (size_t)e * strideB2 + k0_2;

    int tid = threadIdx.x;
    int lane = tid & 31, warp = tid >> 5;
    int wm = warp >> 3, wn = warp & 7;      // 2 x 8 warps, warp tile 64x32

    uint32_t sbase = smem_u32(smem);

    // loader mapping: 4 threads/row; thread covers u32 [c0, c0+8)
    int lrow = tid >> 2;                    // 0..127
    int c0 = (tid & 3) * 8;
    int gm = m0 + lrow;
    int gmc = min(gm, M - 1);

    // LDSM per-lane geometry
    int aRow  = wm * 64 + (lane & 15);            // + mi*16
    int aHalf = lane >> 4;                        // k-half 0/1
    int bRow  = wn * 32 + (lane & 7) + ((lane >> 4) << 3);  // + ni2*16
    int bHalf = (lane >> 3) & 1;

    float acc[4][4][4];
#pragma unroll
    for (int mi = 0; mi < 4; mi++)
#pragma unroll
        for (int ni = 0; ni < 4; ni++)
#pragma unroll
            for (int q = 0; q < 4; q++) acc[mi][ni][q] = 0.f;

    int nch = Klen / 64;

    auto issue = [&](int it) {
        uint32_t soff = (uint32_t)(it % NSTAGE) * STAGE_U32;
        int kt2 = it * 32;
        // A: 128 rows x 32 u32 = 512 threads x 8 u32 (two cpa16)
        {
            uint32_t dst = sbase + (uint32_t)(soff + lrow * PITCH + c0) * 4;
            size_t ga = (size_t)gmc * K2 + kt2 + c0;
            cpa16(dst,      Ap + ga);
            cpa16(dst + 16, Ap + ga + 4);
        }
        // B: 256 rows x 32 u32, 2 row-segments per thread (four cpa16)
#pragma unroll
        for (int j = 0; j < 2; j++) {
            int idx = tid + j * 512;
            int r = idx >> 2;
            int cc = (idx & 3) * 8;
            uint32_t dst = sbase + (uint32_t)(soff + A_U32 + r * PITCH + cc) * 4;
            size_t gb = (size_t)(n0 + r) * K2 + kt2 + cc;
            cpa16(dst,      Bp + gb);
            cpa16(dst + 16, Bp + gb + 4);
        }
        cpa_commit();
    };

    issue(0);
    if (nch > 1) issue(1);
    if (nch > 2) issue(2);

    for (int it = 0; it < nch; it++) {
        // guarantee group `it` arrived; keep up to 2 younger groups in flight
        if (it + 2 < nch)      asm volatile("cp.async.wait_group 2;\n" ::: "memory");
        else if (it + 1 < nch) asm volatile("cp.async.wait_group 1;\n" ::: "memory");
        else                   asm volatile("cp.async.wait_group 0;\n" ::: "memory");
        __syncthreads();   // stage it ready; stage (it-1)%4 consumed & free

        if (it + 3 < nch) issue(it + 3);

        uint32_t sA = sbase + (uint32_t)((it % NSTAGE) * STAGE_U32) * 4;
        uint32_t sB = sA + A_U32 * 4;

        // B fragments double-buffered across ks
        uint32_t bb[2][2][4];
#pragma unroll
        for (int n2 = 0; n2 < 2; n2++) {
            uint32_t ao = (uint32_t)((bRow + n2 * 16) * PITCH + bHalf * 4) * 4;
            ldsm4(bb[0][n2], sB + ao);
        }

#pragma unroll
        for (int ks = 0; ks < 4; ks++) {
            if (ks < 3) {
                int kbn = (ks + 1) * 8;
#pragma unroll
                for (int n2 = 0; n2 < 2; n2++) {
                    uint32_t ao = (uint32_t)((bRow + n2 * 16) * PITCH + kbn + bHalf * 4) * 4;
                    ldsm4(bb[(ks + 1) & 1][n2], sB + ao);
                }
            }
            int kb = ks * 8;
#pragma unroll
            for (int mi = 0; mi < 4; mi++) {
                uint32_t ah[4];
                uint32_t ao = (uint32_t)((aRow + mi * 16) * PITCH + kb + aHalf * 4) * 4;
                ldsm4(ah, sA + ao);
#pragma unroll
                for (int ni = 0; ni < 4; ni++) {
                    mma16816h(acc[mi][ni], ah, &bb[ks & 1][ni >> 1][(ni & 1) * 2]);
                }
            }
        }
    }

    // --- epilogue (both paths write packed fp16x2) ---
#pragma unroll
    for (int mi = 0; mi < 4; mi++) {
#pragma unroll
        for (int ni = 0; ni < 4; ni++) {
            int r0 = m0 + wm * 64 + mi * 16 + (lane >> 2);
            int cc = n0 + wn * 32 + ni * 8 + 2 * (lane & 3);
            float* a = acc[mi][ni];
            if (FUSE_RELU_H) {
                size_t eoff = (size_t)e * ((size_t)CAP * (Nn >> 1));
                if (r0 < M) {
                    Ch[eoff + (size_t)r0 * (Nn >> 1) + (cc >> 1)] =
                        packh(__float2half_rn(fmaxf(a[0], 0.f)), __float2half_rn(fmaxf(a[1], 0.f)));
                }
                if (r0 + 8 < M) {
                    Ch[eoff + (size_t)(r0 + 8) * (Nn >> 1) + (cc >> 1)] =
                        packh(__float2half_rn(fmaxf(a[2], 0.f)), __float2half_rn(fmaxf(a[3], 0.f)));
                }
            } else {
                unsigned* Cp = Cpart + (size_t)sp * partStride2 + (size_t)e * strideC2;
                if (r0 < M)
                    Cp[(size_t)r0 * (Nn >> 1) + (cc >> 1)] =
                        packh(__float2half_rn(a[0]), __float2half_rn(a[1]));
                if (r0 + 8 < M)
                    Cp[(size_t)(r0 + 8) * (Nn >> 1) + (cc >> 1)] =
                        packh(__float2half_rn(a[2]), __float2half_rn(a[3]));
            }
        }
    }
}

// ---------------- 6) combine (fp16 partials) + fused aux loss ----------------
__global__ void combine_kernel(float* __restrict__ y, int out_size)
{
    int t = blockIdx.x;
    int i = threadIdx.x;                    // 256 threads, 4 floats each
    const size_t PS2 = (size_t)EE * CAP * DD / 2;
    float4 acc = make_float4(0.f, 0.f, 0.f, 0.f);
#pragma unroll
    for (int j = 0; j < KTOP; j++) {
        int slot = t * KTOP + j;
        int pos = g_slot_pos[slot];
        if (pos >= 0) {
            int e = g_slot_expert[slot];
            size_t rb = ((size_t)(e * CAP + pos)) * (DD / 2);
#pragma unroll
            for (int s = 0; s < NSPLIT2; s++) {
                uint2 p = *(const uint2*)(g_Part + s * PS2 + rb + 2 * i);
                __half2 h0 = *(__half2*)&p.x;
                __half2 h1 = *(__half2*)&p.y;
                float2 f0 = __half22float2(h0);
                float2 f1 = __half22float2(h1);
                acc.x += f0.x; acc.y += f0.y; acc.z += f1.x; acc.w += f1.y;
            }
        }
    }
    ((float4*)(y + (size_t)t * DD))[i] = acc;

    // fused aux loss (block 0, thread 0)
    if (t == 0 && i == 0) {
        float tc = 0.f, ic = 0.f;
#pragma unroll
        for (int e = 0; e < EE; e++) { tc += (float)g_cnt[e]; ic += g_imp[e]; }
        float aux = 0.f;
#pragma unroll
        for (int e = 0; e < EE; e++) aux += ((float)g_cnt[e] / tc) * (g_imp[e] / ic);
        y[out_size - 1] = aux * (float)EE;
    }
}

// ---------------- launch ----------------
extern "C" void kernel_launch(void* const* d_in, const int* in_sizes, int n_in,
                              void* d_out, int out_size)
{
    const float* x  = (const float*)d_in[0];
    const float* Wg = (const float*)d_in[1];
    const float* W1 = (const float*)d_in[2];
    const float* W2 = (const float*)d_in[3];
    float* y = (float*)d_out;
    (void)in_sizes; (void)n_in;

    cudaFuncSetAttribute(gemm_tc_kernel<true>,  cudaFuncAttributeMaxDynamicSharedMemorySize, GEMM_SMEM_BYTES);
    cudaFuncSetAttribute(gemm_tc_kernel<false>, cudaFuncAttributeMaxDynamicSharedMemorySize, GEMM_SMEM_BYTES);

    unsigned *Xh, *Hh, *W1h, *W2h, *Part;
    cudaGetSymbolAddress((void**)&Xh,  g_Xh);
    cudaGetSymbolAddress((void**)&Hh,  g_Hh);
    cudaGetSymbolAddress((void**)&W1h, g_W1h);
    cudaGetSymbolAddress((void**)&W2h, g_W2h);
    cudaGetSymbolAddress((void**)&Part, g_Part);

    // launch order: GEMM1 is the 4th kernel launch -> ncu captures it
    gating_kernel<<<NN, 128>>>(x, Wg, W1, W2);                           // 1 (+ fused wconv)
    assign_kernel<<<1, 256>>>();                                         // 2
    dispatch_kernel<<<SLOTS, 256>>>(x);                                  // 3

    // GEMM1: H = relu(X @ W1^T); per expert M=cnt, N=DFF, K=DD; fused relu+fp16 store
    {
        dim3 grid(DFF / 256, CAP / 128, EE);                             // 4 (profiled)
        gemm_tc_kernel<true><<<grid, 512, GEMM_SMEM_BYTES>>>(
            Xh, W1h, nullptr, Hh,
            DFF, DD, DD, 1, 0,
            CAP * DD / 2, DFF * DD / 2, 0);
    }

    // GEMM2: Part[s] = H[:, s*1024:(s+1)*1024] @ W2[:, slice]^T (split-K x4, fp16 partials)
    {
        dim3 grid(DD / 256, CAP / 128, EE * NSPLIT2);                    // 5
        gemm_tc_kernel<false><<<grid, 512, GEMM_SMEM_BYTES>>>(
            Hh, W2h, Part, nullptr,
            DD, DFF, DFF / NSPLIT2, NSPLIT2, (long long)EE * CAP * DD / 2,
            CAP * DFF / 2, DD * DFF / 2, CAP * DD / 2);
    }

    combine_kernel<<<NN, 256>>>(y, out_size);                            // 6 (+ fused aux)
}